// round 7
// baseline (speedup 1.0000x reference)
#include <cuda_runtime.h>
#include <cstdint>

// Fixed shapes: B=4, C=32, H=512, W=512
#define Bn 4
#define Cn 32
#define Hn 512
#define Wn 512
#define HWn (Hn * Wn)          // 262144
#define CHWn (Cn * HWn)        // 8388608
#define NTOT (Bn * CHWn)       // 33554432 floats

typedef unsigned long long ull;

// Scratch for the column (H) scans; W-scans are fused into contraction.
__device__ float g_x1[NTOT];   // prefix max along H
__device__ float g_x2[NTOT];   // suffix max along H

// Staging for dup-packed weights/bias (prep kernel -> memcpy -> __constant__)
__device__ ull g_tmpw[5 * 32 * 32];   // [g][c][o] dup-packed {w,w}, 40 KB
__device__ ull g_tmpb[32];

// Constant-bank copies: weight fetches ride the const/uniform port, not L1TEX.
__constant__ ull c_w[5 * 32 * 32];
__constant__ ull c_b[32];

__device__ __forceinline__ float neg_inf() { return __int_as_float(0xff800000); }

// ---------------------------------------------------------------------------
// prep: dup-pack weights {w,w} and bias into staging (then D2D-memcpy to const)
// ---------------------------------------------------------------------------
__global__ void prep_kernel(const float* __restrict__ Wm,
                            const float* __restrict__ bias) {
    int i = blockIdx.x * 256 + threadIdx.x;
    if (i < 5 * 32 * 32) {
        int g = i >> 10, rem = i & 1023, c = rem >> 5, o = rem & 31;
        unsigned int u = __float_as_uint(Wm[o * 160 + g * 32 + c]);
        g_tmpw[i] = (ull)u | ((ull)u << 32);
    }
    if (i < 32) {
        unsigned int u = __float_as_uint(bias[i]);
        g_tmpb[i] = (ull)u | ((ull)u << 32);
    }
}

// ---------------------------------------------------------------------------
// vscan: register-staged segmented scan along H (62us @ 68% DRAM; unchanged).
// ---------------------------------------------------------------------------
__global__ void __launch_bounds__(256) vscan_kernel(const float* __restrict__ x) {
    int tile = blockIdx.x;           // [0, B*C*16)
    int wt   = tile & 15;
    int bc   = tile >> 4;
    int ws   = threadIdx.x & 31;
    int seg  = threadIdx.x >> 5;     // 0..7

    size_t base = (size_t)bc * HWn + (size_t)(wt * 32 + ws)
                + (size_t)seg * 64 * Wn;
    const float* xp = x + base;

    float v[64];
#pragma unroll
    for (int i = 0; i < 64; ++i) v[i] = __ldg(xp + (size_t)i * Wn);

    float m = v[0];
#pragma unroll
    for (int i = 1; i < 64; ++i) m = fmaxf(m, v[i]);

    __shared__ float segmax[8][32];
    segmax[seg][ws] = m;
    __syncthreads();

    float c1 = neg_inf();
    float c2 = neg_inf();
#pragma unroll
    for (int s = 0; s < 8; ++s) {
        float sm = segmax[s][ws];
        if (s < seg) c1 = fmaxf(c1, sm);
        if (s > seg) c2 = fmaxf(c2, sm);
    }

    float* o1 = g_x1 + base;
    float* o2 = g_x2 + base;

    float r = c1;
#pragma unroll
    for (int i = 0; i < 64; ++i) {
        r = fmaxf(r, v[i]);
        o1[(size_t)i * Wn] = r;
    }
    r = c2;
#pragma unroll
    for (int i = 63; i >= 0; --i) {
        r = fmaxf(r, v[i]);
        o2[(size_t)i * Wn] = r;
    }
}

// 16-output x 2-pair FMA group: weights from __constant__ (warp-uniform index
// -> const/uniform port, zero L1TEX wavefronts).
__device__ __forceinline__ void fma16(ull acc[16][2], ull v0, ull v1, int wi) {
#pragma unroll
    for (int i = 0; i < 8; ++i) {
        ull wa = c_w[wi + 2 * i];
        ull wb = c_w[wi + 2 * i + 1];
        asm("fma.rn.f32x2 %0, %1, %2, %0;" : "+l"(acc[2*i][0])   : "l"(v0), "l"(wa));
        asm("fma.rn.f32x2 %0, %1, %2, %0;" : "+l"(acc[2*i][1])   : "l"(v1), "l"(wa));
        asm("fma.rn.f32x2 %0, %1, %2, %0;" : "+l"(acc[2*i+1][0]) : "l"(v0), "l"(wb));
        asm("fma.rn.f32x2 %0, %1, %2, %0;" : "+l"(acc[2*i+1][1]) : "l"(v1), "l"(wb));
    }
}

// ---------------------------------------------------------------------------
// Fused W-scan + contraction. Block = one (b,h) row (2048 blocks, 256 thr).
// Scan phase : warp wi loads channel row once, shfl fwd/bwd cummax, stages
//              x/x3/x4 into smem (48 KB).
// FMA phase  : og = tid>>7 (16-output group x2), pp = tid&127 (4 pixels).
//              Per channel: 3 LDS.128 + 2 LDG.128 values, weights from const,
//              80 fma.rn.f32x2. L1 wavefronts/warp/channel: 60 -> 20.
// ---------------------------------------------------------------------------
__global__ void __launch_bounds__(256, 2) contract_fused_kernel(
    const float* __restrict__ x,
    float* __restrict__ out)
{
    extern __shared__ float smem_dyn[];
    float* xs  = smem_dyn;            // [8][512]
    float* x3s = xs + 8 * 512;        // [8][512]
    float* x4s = x3s + 8 * 512;       // [8][512]

    int tid  = threadIdx.x;
    int lane = tid & 31;
    int wi   = tid >> 5;              // scan phase: channel-in-batch (0..7)
    int og   = tid >> 7;              // FMA phase: output group (0..1), 16 outputs
    int pp   = tid & 127;             // FMA phase: pixel quad (pixels pp*4..pp*4+3)
    int bh   = blockIdx.x;
    int h    = bh & (Hn - 1);
    int b    = bh >> 9;

    size_t rowbase = (size_t)b * CHWn + (size_t)h * Wn;
    size_t pixull  = (rowbase >> 1) + (size_t)(pp << 1);   // ull idx of my 4 px

    ull acc[16][2];
#pragma unroll
    for (int o = 0; o < 16; ++o) {
        ull bv = c_b[og * 16 + o];
        acc[o][0] = bv;
        acc[o][1] = bv;
    }

#pragma unroll 1
    for (int batch = 0; batch < 4; ++batch) {
        // ---------- scan phase: warp wi handles channel c = batch*8 + wi ----------
        {
            int c = batch * 8 + wi;
            const float4* xp = (const float4*)(x + rowbase + (size_t)c * HWn);
            float4* xsp  = (float4*)(xs  + wi * 512);
            float4* x3sp = (float4*)(x3s + wi * 512);
            float4* x4sp = (float4*)(x4s + wi * 512);

            float4 v[4];
#pragma unroll
            for (int ch = 0; ch < 4; ++ch) {
                v[ch] = __ldg(xp + ch * 32 + lane);
                xsp[ch * 32 + lane] = v[ch];
            }

            // forward (x3)
            float carry = neg_inf();
#pragma unroll
            for (int ch = 0; ch < 4; ++ch) {
                float l0 = v[ch].x;
                float l1 = fmaxf(l0, v[ch].y);
                float l2 = fmaxf(l1, v[ch].z);
                float l3 = fmaxf(l2, v[ch].w);
                float incl = l3;
#pragma unroll
                for (int d = 1; d < 32; d <<= 1) {
                    float t = __shfl_up_sync(0xffffffffu, incl, d);
                    if (lane >= d) incl = fmaxf(incl, t);
                }
                float excl = __shfl_up_sync(0xffffffffu, incl, 1);
                float bm = (lane == 0) ? carry : fmaxf(carry, excl);
                float4 r;
                r.x = fmaxf(bm, l0);
                r.y = fmaxf(bm, l1);
                r.z = fmaxf(bm, l2);
                r.w = fmaxf(bm, l3);
                x3sp[ch * 32 + lane] = r;
                carry = fmaxf(carry, __shfl_sync(0xffffffffu, incl, 31));
            }

            // backward (x4)
            carry = neg_inf();
#pragma unroll
            for (int ch = 3; ch >= 0; --ch) {
                float l3 = v[ch].w;
                float l2 = fmaxf(l3, v[ch].z);
                float l1 = fmaxf(l2, v[ch].y);
                float l0 = fmaxf(l1, v[ch].x);
                float incl = l0;
#pragma unroll
                for (int d = 1; d < 32; d <<= 1) {
                    float t = __shfl_down_sync(0xffffffffu, incl, d);
                    if (lane < 32 - d) incl = fmaxf(incl, t);
                }
                float excl = __shfl_down_sync(0xffffffffu, incl, 1);
                float bm = (lane == 31) ? carry : fmaxf(carry, excl);
                float4 r;
                r.x = fmaxf(bm, l0);
                r.y = fmaxf(bm, l1);
                r.z = fmaxf(bm, l2);
                r.w = fmaxf(bm, l3);
                x4sp[ch * 32 + lane] = r;
                carry = fmaxf(carry, __shfl_sync(0xffffffffu, incl, 0));
            }
        }
        __syncthreads();

        // ---------- FMA phase: 8 channels of this batch ----------
#pragma unroll 1
        for (int cc = 0; cc < 8; ++cc) {
            int c = batch * 8 + cc;

            // Global x1/x2 first: in flight under the smem groups below.
            const ulonglong2* p1 = (const ulonglong2*)((const ull*)g_x1
                                   + pixull + (size_t)c * (HWn / 2));
            const ulonglong2* p2 = (const ulonglong2*)((const ull*)g_x2
                                   + pixull + (size_t)c * (HWn / 2));
            ulonglong2 a1 = __ldg(p1);
            ulonglong2 a2 = __ldg(p2);

            ulonglong2 vx = *(const ulonglong2*)(xs  + cc * 512 + (pp << 2));
            ulonglong2 v3 = *(const ulonglong2*)(x3s + cc * 512 + (pp << 2));
            ulonglong2 v4 = *(const ulonglong2*)(x4s + cc * 512 + (pp << 2));

            int wbase = c * 32 + og * 16;    // + g*1024 per group
            fma16(acc, vx.x, vx.y, wbase + 0 * 1024);
            fma16(acc, v3.x, v3.y, wbase + 3 * 1024);
            fma16(acc, v4.x, v4.y, wbase + 4 * 1024);
            fma16(acc, a1.x, a1.y, wbase + 1 * 1024);
            fma16(acc, a2.x, a2.y, wbase + 2 * 1024);
        }
        __syncthreads();   // before next batch overwrites the stage
    }

    // Store: for each o, lanes (pp) write consecutive 16B -> fully coalesced.
#pragma unroll
    for (int o = 0; o < 16; ++o) {
        float* op = out + (size_t)b * CHWn + (size_t)(og * 16 + o) * HWn
                        + (size_t)h * Wn + (size_t)(pp << 2);
        ulonglong2 r;
        r.x = acc[o][0];
        r.y = acc[o][1];
        *(ulonglong2*)op = r;
    }
}

// ---------------------------------------------------------------------------
extern "C" void kernel_launch(void* const* d_in, const int* in_sizes, int n_in,
                              void* d_out, int out_size) {
    const float* x    = (const float*)d_in[0];   // [4,32,512,512]
    const float* Wm   = (const float*)d_in[1];   // [32,160,1,1]
    const float* bias = (const float*)d_in[2];   // [32]
    float* out = (float*)d_out;                  // [4,32,512,512]

    constexpr int SMEM_BYTES = 3 * 8 * 512 * 4;  // 49152
    cudaFuncSetAttribute(contract_fused_kernel,
                         cudaFuncAttributeMaxDynamicSharedMemorySize, SMEM_BYTES);

    // Stage dup-packed weights/bias, then D2D-copy into the constant bank.
    prep_kernel<<<20, 256>>>(Wm, bias);
    void* tmpw_ptr = nullptr;
    void* tmpb_ptr = nullptr;
    cudaGetSymbolAddress(&tmpw_ptr, g_tmpw);
    cudaGetSymbolAddress(&tmpb_ptr, g_tmpb);
    cudaMemcpyToSymbolAsync(c_w, tmpw_ptr, sizeof(ull) * 5 * 32 * 32, 0,
                            cudaMemcpyDeviceToDevice, 0);
    cudaMemcpyToSymbolAsync(c_b, tmpb_ptr, sizeof(ull) * 32, 0,
                            cudaMemcpyDeviceToDevice, 0);

    vscan_kernel<<<Bn * Cn * (Wn / 32), 256>>>(x);                 // 2048 blocks
    contract_fused_kernel<<<Bn * Hn, 256, SMEM_BYTES>>>(x, out);   // 2048 blocks
}